// round 9
// baseline (speedup 1.0000x reference)
#include <cuda_runtime.h>
#include <math.h>

// ---------------- Problem constants ----------------
#define Bn 8
#define Dn 64
#define Hn 256
#define Wn 256
#define Kn 49
#define HWn (Hn*Wn)
#define Pn (Bn*HWn)             // 524288 pixels

// ---------------- Tiling ----------------
#define TX 32                   // tile width (pixels)
#define TY 16                   // tile height
#define HX 38                   // halo width (TX+6)
#define NHRmax 19               // max halo rows per K-half (NR+15)
#define HXP 40                  // padded vis pitch (conflict-free LDS.64)
#define TXP 36                  // padded rubin pitch (16B rows for cp.async.16)
#define DC 4                    // channels per chunk
#define NCH (Dn/DC)             // 16 chunks

#define VIS_ELE (DC*NHRmax*HXP)   // 3040 floats
#define RUB_ELE (DC*TY*TXP)       // 2304 floats
#define BUF_ELE (VIS_ELE+RUB_ELE) // 5344 floats; x2 = 42752 B < 48KB static

#define TILES_X (Wn/TX)         // 8
#define TILES_Y (Hn/TY)         // 16
#define TILES_PER_B (TILES_X*TILES_Y)  // 128
#define NBLK (Bn*TILES_PER_B)   // 1024

// ---------------- Output layout (flattened tuple concat) ----------------
#define OFF_DY 0
#define OFF_DX ((size_t)Pn)
#define OFF_CL ((size_t)2*Pn)
#define OFF_CG ((size_t)3*Pn)
#define OFF_LW ((size_t)3*Pn+8)
#define OFF_LG ((size_t)4*Pn+8)

// ---------------- Scratch (device globals; no allocation allowed) ----------------
__device__ float g_part[NBLK*Kn];
__device__ float g_dyg[Bn];
__device__ float g_dxg[Bn];

__device__ __forceinline__ void cpa4(float* smem_dst, const float* gsrc) {
    unsigned s = (unsigned)__cvta_generic_to_shared(smem_dst);
    asm volatile("cp.async.ca.shared.global [%0], [%1], 4;" :: "r"(s), "l"(gsrc));
}
__device__ __forceinline__ void cpa16(float* smem_dst, const float* gsrc) {
    unsigned s = (unsigned)__cvta_generic_to_shared(smem_dst);
    asm volatile("cp.async.cg.shared.global [%0], [%1], 16;" :: "r"(s), "l"(gsrc));
}

// ---- staging: one D-chunk, fully hoisted addressing ----
template<int NHR>
__device__ __forceinline__ void stage_chunk(float* __restrict__ buf,
        const float* __restrict__ rubb0, const float* __restrict__ visb0, int d0,
        const int* vgo, const int* vso, int nvo, int rgo, int rso, int dhalf)
{
    const float* visb = visb0 + (size_t)d0 * HWn;
    #pragma unroll
    for (int d = 0; d < DC; ++d) {
        float* vb = buf + d*(NHR*HXP);
        const float* vg = visb + (size_t)d*HWn;
        #pragma unroll
        for (int j = 0; j < 3; ++j)
            if (j < nvo) cpa4(vb + vso[j], vg + vgo[j]);
    }
    const float* rubb = rubb0 + (size_t)(d0 + dhalf*2) * HWn;
    float* rbuf = buf + DC*(NHR*HXP) + (dhalf*2)*(TY*TXP);
    cpa16(rbuf + rso,            rubb + rgo);
    cpa16(rbuf + (TY*TXP) + rso, rubb + (size_t)HWn + rgo);
}

// ---- compute: one D-chunk, 2 horizontal pixels/thread, all LDS.64 ----
template<int NHR, int NR>
__device__ __forceinline__ void compute_chunk(const float* __restrict__ buf,
        int ty, int tx2,
        float* __restrict__ acc0, float* __restrict__ acc1,
        float& ss0, float& ss1,
        float* __restrict__ vss, const int* vso, int nvo)
{
    const float* rub = buf + DC*(NHR*HXP);
    #pragma unroll
    for (int d = 0; d < DC; ++d) {
        float2 ru = *(const float2*)(rub + d*(TY*TXP) + ty*TXP + tx2);
        const float rx = ru.x, ry = ru.y;
        ss0 = fmaf(rx, rx, ss0);
        ss1 = fmaf(ry, ry, ss1);
        const float* vplane = buf + d*(NHR*HXP);
        #pragma unroll
        for (int r = 0; r < NR; ++r) {
            const float2* vr = (const float2*)(vplane + (ty + r)*HXP + tx2);
            float2 p0 = vr[0], p1 = vr[1], p2 = vr[2], p3 = vr[3];
            const int kb = r*7;
            acc0[kb+0] = fmaf(rx, p0.x, acc0[kb+0]);
            acc1[kb+0] = fmaf(ry, p0.y, acc1[kb+0]);
            acc0[kb+1] = fmaf(rx, p0.y, acc0[kb+1]);
            acc1[kb+1] = fmaf(ry, p1.x, acc1[kb+1]);
            acc0[kb+2] = fmaf(rx, p1.x, acc0[kb+2]);
            acc1[kb+2] = fmaf(ry, p1.y, acc1[kb+2]);
            acc0[kb+3] = fmaf(rx, p1.y, acc0[kb+3]);
            acc1[kb+3] = fmaf(ry, p2.x, acc1[kb+3]);
            acc0[kb+4] = fmaf(rx, p2.x, acc0[kb+4]);
            acc1[kb+4] = fmaf(ry, p2.y, acc1[kb+4]);
            acc0[kb+5] = fmaf(rx, p2.y, acc0[kb+5]);
            acc1[kb+5] = fmaf(ry, p3.x, acc1[kb+5]);
            acc0[kb+6] = fmaf(rx, p3.x, acc0[kb+6]);
            acc1[kb+6] = fmaf(ry, p3.y, acc1[kb+6]);
        }
        #pragma unroll
        for (int j = 0; j < 3; ++j)
            if (j < nvo) {
                float v = vplane[vso[j]];
                vss[j] = fmaf(v, v, vss[j]);
            }
    }
}

// ---------------- Main kernel body (one K-half) ----------------
// R0 = first tap row, NR = tap rows. Halo rows staged: R0-3 .. R0+NR+12 rel y0.
template<int R0, int NR>
__device__ __forceinline__ void main_body(
        float* __restrict__ sm,
        const float* __restrict__ rubin, const float* __restrict__ vis,
        float* __restrict__ out, int bx, int by, int b)
{
    constexpr int NHR = NR + 15;      // halo rows this half
    constexpr int NVV = NHR * HX;     // halo vectors
    constexpr int NK  = NR * 7;       // taps this half

    float* buf0 = sm;
    float* buf1 = sm + BUF_ELE;
    float* vinv  = sm;                // reuse after mainloop: NHR*HXP <= 760
    float* sredw = sm + 768;          // 8 warps * 28 max

    const int tx = threadIdx.x, ty = threadIdx.y;
    const int tid = ty*16 + tx;
    const int x0 = bx*TX, y0 = by*TY;
    const int tx2 = 2*tx;

    // ---- hoisted staging addresses (chunk-invariant) ----
    const int nvo = (tid + 512 < NVV) ? 3 : 2;
    int vgo[3], vso[3];
    #pragma unroll
    for (int j = 0; j < 3; ++j) {
        int v = tid + 256*j;
        int row = v / HX;
        int col = v - row*HX;
        int gy = min(Hn-1, max(0, y0 - 3 + R0 + row));
        int gx = min(Wn-1, max(0, x0 - 3 + col));
        vgo[j] = gy*Wn + gx;
        vso[j] = row*HXP + col;
    }
    const int quad = tid & 127, dhalf = tid >> 7;
    const int rr_ = quad >> 3, rc = (quad & 7) << 2;
    const int rgo = rr_*Wn + rc;
    const int rso = rr_*TXP + rc;

    const float* rubb0 = rubin + (size_t)b*Dn*HWn + (size_t)y0*Wn + x0;
    const float* visb0 = vis   + (size_t)b*Dn*HWn;

    float acc0[NK], acc1[NK];
    #pragma unroll
    for (int k = 0; k < NK; ++k) { acc0[k] = 0.f; acc1[k] = 0.f; }
    float ss0 = 0.f, ss1 = 0.f;
    float vss[3] = {0.f, 0.f, 0.f};

    // ---- software-pipelined chunk loop (cp.async double buffer) ----
    stage_chunk<NHR>(buf0, rubb0, visb0, 0, vgo, vso, nvo, rgo, rso, dhalf);
    asm volatile("cp.async.commit_group;" ::: "memory");
    #pragma unroll 1
    for (int ch = 0; ch < NCH; ++ch) {
        if (ch + 1 < NCH) {
            stage_chunk<NHR>(((ch+1) & 1) ? buf1 : buf0, rubb0, visb0, (ch+1)*DC,
                             vgo, vso, nvo, rgo, rso, dhalf);
            asm volatile("cp.async.commit_group;" ::: "memory");
            asm volatile("cp.async.wait_group 1;" ::: "memory");
        } else {
            asm volatile("cp.async.wait_group 0;" ::: "memory");
        }
        __syncthreads();
        compute_chunk<NHR, NR>((ch & 1) ? buf1 : buf0, ty, tx2,
                               acc0, acc1, ss0, ss1, vss, vso, nvo);
        __syncthreads();
    }

    // ---- inverse norms (matches reference: x / max(|x|,1e-6)) ----
    float inv0 = 1.f / fmaxf(sqrtf(ss0), 1e-6f);
    float inv1 = 1.f / fmaxf(sqrtf(ss1), 1e-6f);
    #pragma unroll
    for (int j = 0; j < 3; ++j)
        if (j < nvo) vinv[vso[j]] = 1.f / fmaxf(sqrtf(vss[j]), 1e-6f);
    __syncthreads();

    const float s0 = inv0 * 0.125f;
    const float s1 = inv1 * 0.125f;
    #pragma unroll
    for (int r = 0; r < NR; ++r) {
        const float2* vr = (const float2*)(vinv + (ty + r)*HXP + tx2);
        float2 p0 = vr[0], p1 = vr[1], p2 = vr[2], p3 = vr[3];
        const int kb = r*7;
        acc0[kb+0] *= s0 * p0.x;  acc1[kb+0] *= s1 * p0.y;
        acc0[kb+1] *= s0 * p0.y;  acc1[kb+1] *= s1 * p1.x;
        acc0[kb+2] *= s0 * p1.x;  acc1[kb+2] *= s1 * p1.y;
        acc0[kb+3] *= s0 * p1.y;  acc1[kb+3] *= s1 * p2.x;
        acc0[kb+4] *= s0 * p2.x;  acc1[kb+4] *= s1 * p2.y;
        acc0[kb+5] *= s0 * p2.y;  acc1[kb+5] *= s1 * p3.x;
        acc0[kb+6] *= s0 * p3.x;  acc1[kb+6] *= s1 * p3.y;
    }

    // ---- write logits (global k = R0*7 + kk) ----
    {
        const size_t base = OFF_LG + (size_t)b*Kn*HWn + (size_t)(R0*7)*HWn
                          + (size_t)(y0+ty)*Wn + (x0 + tx2);
        #pragma unroll
        for (int k = 0; k < NK; ++k) {
            *(float2*)(out + base + (size_t)k*HWn) = make_float2(acc0[k], acc1[k]);
        }
    }

    // ---- deterministic partial sums for global mean ----
    {
        const int lane = tid & 31, w = tid >> 5;
        #pragma unroll
        for (int k = 0; k < NK; ++k) {
            float s = acc0[k] + acc1[k];
            s += __shfl_down_sync(0xffffffffu, s, 16);
            s += __shfl_down_sync(0xffffffffu, s, 8);
            s += __shfl_down_sync(0xffffffffu, s, 4);
            s += __shfl_down_sync(0xffffffffu, s, 2);
            s += __shfl_down_sync(0xffffffffu, s, 1);
            if (lane == 0) sredw[w*28 + k] = s;
        }
        __syncthreads();
        if (tid < NK) {
            float t = 0.f;
            #pragma unroll
            for (int w2 = 0; w2 < 8; ++w2) t += sredw[w2*28 + tid];
            int blk = (b*TILES_Y + by)*TILES_X + bx;
            g_part[(size_t)blk*Kn + R0*7 + tid] = t;
        }
    }
}

__global__ void __launch_bounds__(256, 2)
ccb_main_kernel_a(const float* __restrict__ rubin, const float* __restrict__ vis,
                  float* __restrict__ out)
{
    __shared__ __align__(16) float sm[2*BUF_ELE];
    main_body<0, 4>(sm, rubin, vis, out, blockIdx.x, blockIdx.y, blockIdx.z);
}

__global__ void __launch_bounds__(256, 2)
ccb_main_kernel_b(const float* __restrict__ rubin, const float* __restrict__ vis,
                  float* __restrict__ out)
{
    __shared__ __align__(16) float sm[2*BUF_ELE];
    main_body<4, 3>(sm, rubin, vis, out, blockIdx.x, blockIdx.y, blockIdx.z);
}

// ---------------- Global-softmax kernel ----------------
__global__ void ccb_global_kernel(const float* __restrict__ logt, float* __restrict__ out)
{
    const int b = blockIdx.x;
    const int tid = threadIdx.x;   // 64 threads
    __shared__ float lg[Kn];
    if (tid < Kn) {
        float s = 0.f;
        const float* p = g_part + (size_t)(b*TILES_PER_B)*Kn + tid;
        #pragma unroll 4
        for (int t = 0; t < TILES_PER_B; ++t) s += p[(size_t)t*Kn];
        lg[tid] = s * (1.0f/(float)HWn);
    }
    __syncthreads();
    if (tid == 0) {
        const float tau  = fmaxf(__expf(logt[0]), 1e-3f);
        const float itau = 1.f / tau;
        float m = lg[0];
        #pragma unroll
        for (int k = 1; k < Kn; ++k) m = fmaxf(m, lg[k]);
        float s = 0.f, wy = 0.f, wx = 0.f;
        #pragma unroll
        for (int k = 0; k < Kn; ++k) {
            float e = __expf((lg[k] - m)*itau);
            s += e;
            wy += e * (float)(k/7 - 3);
            wx += e * (float)(k%7 - 3);
        }
        float is = 1.f/s;
        out[OFF_CG + b] = is;       // conf_global
        g_dyg[b] = wy*is;
        g_dxg[b] = wx*is;
    }
}

// ---------------- Fused epilogue: local softmax + blend ----------------
__global__ void __launch_bounds__(256)
ccb_post_kernel(const float* __restrict__ logt, float* __restrict__ out)
{
    const int hw = blockIdx.x*256 + threadIdx.x;   // 0..HWn-1
    const int b  = blockIdx.y;
    const size_t i = (size_t)b*HWn + hw;

    const float* lg = out + OFF_LG + (size_t)b*Kn*HWn + hw;
    float l[Kn];
    #pragma unroll
    for (int k = 0; k < Kn; ++k) l[k] = lg[(size_t)k*HWn];

    const float tau  = fmaxf(__expf(logt[0]), 1e-3f);
    const float itau = 1.f / tau;

    float m = l[0];
    #pragma unroll
    for (int k = 1; k < Kn; ++k) m = fmaxf(m, l[k]);
    float s = 0.f, wy = 0.f, wx = 0.f;
    #pragma unroll
    for (int k = 0; k < Kn; ++k) {
        float e = __expf((l[k] - m)*itau);
        s += e;
        wy += e * (float)(k/7 - 3);
        wx += e * (float)(k%7 - 3);
    }
    float is  = 1.f/s;
    float cf  = is;                 // max prob
    float dyl = wy*is;
    float dxl = wx*is;

    const float uni = 1.0f/(float)Kn;
    float lw = fminf(fmaxf((cf - uni)*(1.0f/(1.0f - uni)), 0.f), 1.f);
    float gw = 1.0f - lw;

    out[OFF_DY + i] = lw*dyl + gw*g_dyg[b];
    out[OFF_DX + i] = lw*dxl + gw*g_dxg[b];
    out[OFF_CL + i] = cf;
    out[OFF_LW + i] = lw;
}

extern "C" void kernel_launch(void* const* d_in, const int* in_sizes, int n_in,
                              void* d_out, int out_size) {
    const float* rubin = (const float*)d_in[0];
    const float* vis   = (const float*)d_in[1];
    const float* logt  = (const float*)d_in[2];
    float* out = (float*)d_out;
    (void)in_sizes; (void)n_in; (void)out_size;

    dim3 grid(TILES_X, TILES_Y, Bn);
    dim3 blk(16, 16, 1);
    ccb_main_kernel_a<<<grid, blk>>>(rubin, vis, out);
    ccb_main_kernel_b<<<grid, blk>>>(rubin, vis, out);
    ccb_global_kernel<<<Bn, 64>>>(logt, out);
    dim3 pgrid(HWn/256, Bn);
    ccb_post_kernel<<<pgrid, 256>>>(logt, out);
}